// round 12
// baseline (speedup 1.0000x reference)
#include <cuda_runtime.h>
#include <cuda_bf16.h>
#include <math.h>

#define BATCH  64
#define NPTS   128
#define FEAT   4
#define HID    100
#define NPAIRS 8128   // C(128,2)

// Per-point projections (k-major), produced by prep_kernel:
//   g_A [b][k][i] = d[k] + x[b][i] . M[0:4][k]   (bias folded)
//   g_C2[b][k][j] = (c, c)  where c = x[b][j] . M[4:8][k]   (pre-duplicated)
__device__ __align__(16) float  g_A [BATCH * HID * NPTS];    // 3.28 MB
__device__ __align__(16) float2 g_C2[BATCH * HID * NPTS];    // 6.55 MB

// 32x32 tile list over the 4x4 upper triangle (jt >= it): 10 tiles
__constant__ unsigned char TCI[10] = {0,0,0,0, 1,1,1, 2,2, 3};
__constant__ unsigned char TCJ[10] = {0,1,2,3, 1,2,3, 2,3, 3};

// ---- packed f32x2 helpers (sm_100+) --------------------------------------
__device__ __forceinline__ unsigned long long f2_add(unsigned long long a,
                                                     unsigned long long b) {
    unsigned long long d;
    asm("add.rn.f32x2 %0, %1, %2;" : "=l"(d) : "l"(a), "l"(b));
    return d;
}
__device__ __forceinline__ unsigned long long f2_fma(unsigned long long a,
                                                     unsigned long long b,
                                                     unsigned long long c) {
    unsigned long long d;
    asm("fma.rn.f32x2 %0, %1, %2, %3;" : "=l"(d) : "l"(a), "l"(b), "l"(c));
    return d;
}
__device__ __forceinline__ unsigned long long f2_pack(float lo, float hi) {
    unsigned long long d;
    asm("mov.b64 %0, {%1, %2};" : "=l"(d) : "f"(lo), "f"(hi));
    return d;
}
__device__ __forceinline__ void f2_unpack(unsigned long long v, float& lo, float& hi) {
    asm("mov.b64 {%0, %1}, %2;" : "=f"(lo), "=f"(hi) : "l"(v));
}
__device__ __forceinline__ unsigned long long f2_relu(unsigned long long t) {
    float lo, hi;
    f2_unpack(t, lo, hi);
    lo = fmaxf(lo, 0.f);
    hi = fmaxf(hi, 0.f);
    return f2_pack(lo, hi);
}

// ---------------------------------------------------------------------------
// Kernel 1: prep.  One CTA per k (grid 100, 256 threads).
// Phase A: fold column k (warps 0-3 partial over t, smem reduce).
// Phase B: project all 8192 (b, point) pairs for this k; write A and
// pre-duplicated C2 (coalesced stores, k-row contiguous).
// ---------------------------------------------------------------------------
__global__ __launch_bounds__(256)
void prep_kernel(const float* __restrict__ x,    // [64,128,4]
                 const float* __restrict__ W1,   // [8,100]
                 const float* __restrict__ b1,   // [100]
                 const float* __restrict__ W2,   // [100,100]
                 const float* __restrict__ b2)   // [100]
{
    __shared__ __align__(16) float W1s[8 * HID];
    __shared__ float b1s[HID];
    __shared__ float red[4 * 9];
    __shared__ float Mf[9];

    const int k   = blockIdx.x;
    const int tid = threadIdx.x;
    const int wid = tid >> 5;
    const int lid = tid & 31;

    // stage W1 (800 floats) + b1 (100)
    for (int q = tid; q < 200; q += 256)
        reinterpret_cast<float4*>(W1s)[q] = reinterpret_cast<const float4*>(W1)[q];
    if (tid < 25)
        reinterpret_cast<float4*>(b1s)[tid] = reinterpret_cast<const float4*>(b1)[tid];
    __syncthreads();

    // fold: warps 0-3 each cover a 32-wide t-slab
    if (wid < 4) {
        int t = wid * 32 + lid;
        float acc[9] = {0.f,0.f,0.f,0.f,0.f,0.f,0.f,0.f,0.f};
        if (t < HID) {
            float w2 = __ldg(W2 + t * HID + k);
            #pragma unroll
            for (int f = 0; f < 8; f++)
                acc[f] = W1s[f * HID + t] * w2;
            acc[8] = b1s[t] * w2;
        }
        #pragma unroll
        for (int off = 16; off > 0; off >>= 1) {
            #pragma unroll
            for (int q = 0; q < 9; q++)
                acc[q] += __shfl_down_sync(0xffffffffu, acc[q], off);
        }
        if (lid == 0) {
            #pragma unroll
            for (int q = 0; q < 9; q++)
                red[wid * 9 + q] = acc[q];
        }
    }
    __syncthreads();
    if (tid < 9) {
        float v = red[tid] + red[9 + tid] + red[18 + tid] + red[27 + tid];
        if (tid == 8) v += __ldg(b2 + k);      // d = b2[k] + b1 @ W2[:,k]
        Mf[tid] = v;
    }
    __syncthreads();

    // projection: all 256 threads sweep 8192 (b, i) points
    const float m0 = Mf[0], m1 = Mf[1], m2 = Mf[2], m3 = Mf[3];
    const float m4 = Mf[4], m5 = Mf[5], m6 = Mf[6], m7 = Mf[7];
    const float dk = Mf[8];
    const float4* x4 = reinterpret_cast<const float4*>(x);

    #pragma unroll 4
    for (int e = tid; e < BATCH * NPTS; e += 256) {
        int b = e >> 7;
        int i = e & (NPTS - 1);
        float4 xv = __ldg(x4 + e);
        float a = dk;
        a = fmaf(xv.x, m0, a); a = fmaf(xv.y, m1, a);
        a = fmaf(xv.z, m2, a); a = fmaf(xv.w, m3, a);
        float c;
        c =      xv.x * m4;    c = fmaf(xv.y, m5, c);
        c = fmaf(xv.z, m6, c); c = fmaf(xv.w, m7, c);
        unsigned int off = ((unsigned int)b * HID + (unsigned int)k) * NPTS + (unsigned int)i;
        g_A[off]  = a;
        g_C2[off] = make_float2(c, c);
    }
}

// ---------------------------------------------------------------------------
// Kernel 2: pair tiles.  32x32 tile, 256 threads = 4 k-groups x 64.
// Prologue: pure L2->smem staging of A row-block and pre-duplicated C2.
// Main loop: 4i x 4j f32x2 slots; cd comes straight from cS2 (no dup MOVs).
// redS aliases the (dead) aS/cS2 region after the main loop.
// Grid (10 tiles, 64 batches) = 640 CTAs, 39.2 KB smem -> 5 CTAs/SM, 1 wave.
// ---------------------------------------------------------------------------
__global__ __launch_bounds__(256, 5)
void pair_kernel(const float* __restrict__ W3,   // [100]
                 const float* __restrict__ b3,   // [1]
                 float* __restrict__ out)        // [64, 8128]
{
    __shared__ __align__(16) char smemU[HID * 32 * 4 + HID * 32 * 8];  // 38.4 KB
    __shared__ __align__(8)  float2 wS[HID];                           // 0.8 KB

    float*              aS   = reinterpret_cast<float*>(smemU);                  // [k][32]
    unsigned long long* cS2  = reinterpret_cast<unsigned long long*>(smemU + HID * 32 * 4); // [k][32] (c,c)
    unsigned long long* redS = reinterpret_cast<unsigned long long*>(smemU);     // 8*256 u64, post-main

    const int tid  = threadIdx.x;
    const int tile = blockIdx.x;
    const int b    = blockIdx.y;
    const int i0   = TCI[tile] * 32;
    const int j0   = TCJ[tile] * 32;

    const int kg  = tid >> 6;        // k-group 0..3
    const int t64 = tid & 63;
    const int tj  = t64 & 7;         // 8 j-groups of 4
    const int ti  = t64 >> 3;        // 8 i-groups of 4

    // --- prologue: stage A (800 f4) and C2 (1600 f4) from L2; W3 dup ---
    {
        // A: float4 view.  base in float4 units: (b*HID*NPTS + k*NPTS + i0)/4
        const float4* A4 = reinterpret_cast<const float4*>(g_A);
        const unsigned int baseA4 = ((unsigned int)b * HID * NPTS + i0) >> 2;
        for (int q = tid; q < 800; q += 256) {
            int k = q >> 3, m = q & 7;
            reinterpret_cast<float4*>(aS)[k * 8 + m] =
                __ldg(A4 + baseA4 + (unsigned int)k * (NPTS >> 2) + m);
        }
        // C2: float4 view over float2 data.  base in float4 units:
        // (b*HID*NPTS + k*NPTS + j0) float2 elements / 2
        const float4* C4 = reinterpret_cast<const float4*>(g_C2);
        const unsigned int baseC4 = ((unsigned int)b * HID * NPTS + j0) >> 1;
        for (int q = tid; q < 1600; q += 256) {
            int k = q >> 4, m = q & 15;
            reinterpret_cast<float4*>(cS2)[k * 16 + m] =
                __ldg(C4 + baseC4 + (unsigned int)k * (NPTS >> 1) + m);
        }
        if (tid < HID) {
            float w = __ldg(W3 + tid);
            wS[tid] = make_float2(w, w);
        }
    }
    __syncthreads();

    // --- main loop: 16 slots per thread, 25 k's per group, packed f32x2 ---
    unsigned long long acc[8] = {0ull,0ull,0ull,0ull,0ull,0ull,0ull,0ull};
    const float*              aP = aS  + ti * 4;
    const unsigned long long* cP = cS2 + tj * 4;
    const unsigned long long* wP = reinterpret_cast<const unsigned long long*>(wS);
    const int kEnd = kg * 25 + 25;

    #pragma unroll 5
    for (int k = kg * 25; k < kEnd; k++) {
        float4 a4 = *reinterpret_cast<const float4*>(aP + k * 32);  // LDS.128
        unsigned long long w2 = wP[k];                               // LDS.64 bcast
        unsigned long long A01 = f2_pack(a4.x, a4.y);
        unsigned long long A23 = f2_pack(a4.z, a4.w);
        #pragma unroll
        for (int jr = 0; jr < 4; jr++) {
            unsigned long long cd = cP[k * 32 + jr];                 // LDS.64, pre-dup
            unsigned long long t0 = f2_relu(f2_add(A01, cd));
            unsigned long long t1 = f2_relu(f2_add(A23, cd));
            acc[jr * 2 + 0] = f2_fma(t0, w2, acc[jr * 2 + 0]);
            acc[jr * 2 + 1] = f2_fma(t1, w2, acc[jr * 2 + 1]);
        }
    }
    __syncthreads();   // aS/cS2 dead; safe to overwrite with redS

    // --- all groups publish partials (conflict-free: t64 fastest) ---
    #pragma unroll
    for (int q = 0; q < 8; q++)
        redS[q * 256 + kg * 64 + t64] = acc[q];
    __syncthreads();

    // --- distributed finalize: group kg handles jr = kg, both i-halves ---
    {
        const int jr = kg;
        unsigned long long s0, s1;
        {
            const unsigned long long* r0 = redS + (jr * 2 + 0) * 256 + t64;
            const unsigned long long* r1 = redS + (jr * 2 + 1) * 256 + t64;
            s0 = f2_add(f2_add(r0[0], r0[64]), f2_add(r0[128], r0[192]));
            s1 = f2_add(f2_add(r1[0], r1[64]), f2_add(r1[128], r1[192]));
        }
        const float bias3 = __ldg(b3);
        float* outb = out + (size_t)b * NPAIRS;
        int j = j0 + tj * 4 + jr;
        float v[4];
        f2_unpack(s0, v[0], v[1]);
        f2_unpack(s1, v[2], v[3]);
        #pragma unroll
        for (int pi = 0; pi < 4; pi++) {
            int i = i0 + ti * 4 + pi;
            if (j > i) {
                int rb = i * (NPTS - 1) - ((i * (i - 1)) >> 1) - i - 1;
                float s = bias3 + v[pi];
                outb[rb + j] = __fdividef(1.f, 1.f + __expf(-s));
            }
        }
    }
}

// ---------------------------------------------------------------------------
extern "C" void kernel_launch(void* const* d_in, const int* in_sizes, int n_in,
                              void* d_out, int out_size)
{
    const float* x   = (const float*)d_in[0];
    // d_in[1] = in_hitnr (unused by the reference)
    const float* W1  = (const float*)d_in[2];
    const float* b1  = (const float*)d_in[3];
    const float* W2  = (const float*)d_in[4];
    const float* b2  = (const float*)d_in[5];
    const float* W3  = (const float*)d_in[6];
    const float* b3  = (const float*)d_in[7];
    float* out = (float*)d_out;

    prep_kernel<<<HID, 256>>>(x, W1, b1, W2, b2);
    pair_kernel<<<dim3(10, BATCH), 256>>>(W3, b3, out);
}

// round 13
// speedup vs baseline: 1.4108x; 1.4108x over previous
#include <cuda_runtime.h>
#include <cuda_bf16.h>
#include <math.h>

#define BATCH  64
#define NPTS   128
#define FEAT   4
#define HID    100
#define NPAIRS 8128   // C(128,2)

// Folded weights: g_M[f][k] = sum_t W1[f][t]*W2[t][k] (f 0..7)
//                 g_d[k]    = b2[k] + sum_t b1[t]*W2[t][k]
__device__ __align__(16) float g_M[8 * HID];
__device__ __align__(16) float g_d[HID];

// 32x32 tile list over the 4x4 upper triangle (jt >= it): 10 tiles
__constant__ unsigned char TCI[10] = {0,0,0,0, 1,1,1, 2,2, 3};
__constant__ unsigned char TCJ[10] = {0,1,2,3, 1,2,3, 2,3, 3};

// ---- packed f32x2 helpers (sm_100+) --------------------------------------
__device__ __forceinline__ unsigned long long f2_add(unsigned long long a,
                                                     unsigned long long b) {
    unsigned long long d;
    asm("add.rn.f32x2 %0, %1, %2;" : "=l"(d) : "l"(a), "l"(b));
    return d;
}
__device__ __forceinline__ unsigned long long f2_fma(unsigned long long a,
                                                     unsigned long long b,
                                                     unsigned long long c) {
    unsigned long long d;
    asm("fma.rn.f32x2 %0, %1, %2, %3;" : "=l"(d) : "l"(a), "l"(b), "l"(c));
    return d;
}
__device__ __forceinline__ unsigned long long f2_pack(float lo, float hi) {
    unsigned long long d;
    asm("mov.b64 %0, {%1, %2};" : "=l"(d) : "f"(lo), "f"(hi));
    return d;
}
__device__ __forceinline__ void f2_unpack(unsigned long long v, float& lo, float& hi) {
    asm("mov.b64 {%0, %1}, %2;" : "=f"(lo), "=f"(hi) : "l"(v));
}
__device__ __forceinline__ unsigned long long f2_relu(unsigned long long t) {
    float lo, hi;
    f2_unpack(t, lo, hi);
    lo = fmaxf(lo, 0.f);
    hi = fmaxf(hi, 0.f);
    return f2_pack(lo, hi);
}

// ---------------------------------------------------------------------------
// Kernel 1: fold.  One warp per k (grid 100).  Lane-strided t, shfl-reduce.
// ---------------------------------------------------------------------------
__global__ __launch_bounds__(32)
void fold_kernel(const float* __restrict__ W1,   // [8,100]
                 const float* __restrict__ b1,   // [100]
                 const float* __restrict__ W2,   // [100,100]
                 const float* __restrict__ b2)   // [100]
{
    const int k   = blockIdx.x;
    const int lid = threadIdx.x;

    float acc[9] = {0.f,0.f,0.f,0.f,0.f,0.f,0.f,0.f,0.f};
    #pragma unroll
    for (int tb = 0; tb < 4; tb++) {
        int t = lid + tb * 32;
        if (t < HID) {
            float w2 = W2[t * HID + k];
            #pragma unroll
            for (int f = 0; f < 8; f++)
                acc[f] = fmaf(W1[f * HID + t], w2, acc[f]);
            acc[8] = fmaf(b1[t], w2, acc[8]);
        }
    }
    #pragma unroll
    for (int off = 16; off > 0; off >>= 1) {
        #pragma unroll
        for (int q = 0; q < 9; q++)
            acc[q] += __shfl_down_sync(0xffffffffu, acc[q], off);
    }
    if (lid == 0) {
        #pragma unroll
        for (int f = 0; f < 8; f++)
            g_M[f * HID + k] = acc[f];
        g_d[k] = acc[8] + b2[k];
    }
}

// ---------------------------------------------------------------------------
// Kernel 2: pair tiles with fused projection.  4 CTAs/SM (reg cap 64) and an
// explicitly software-pipelined main loop (double-buffered a4/c4/w2).
// 32x32 tile, 256 threads = 4 k-groups x 64.  4i x 4j f32x2 slots per thread.
// aS/cS/wS padded by one k-row so the k+1 prefetch at strip end is in-bounds.
// Grid (10 tiles, 64 batches) = 640 CTAs.
// ---------------------------------------------------------------------------
__global__ __launch_bounds__(256, 4)
void pair_kernel(const float* __restrict__ x,    // [64,128,4]
                 const float* __restrict__ W3,   // [100]
                 const float* __restrict__ b3,   // [1]
                 float* __restrict__ out)        // [64, 8128]
{
    __shared__ __align__(16) float aS[(HID + 1) * 32];          // 12.93 KB
    __shared__ __align__(16) float cS[(HID + 1) * 32];          // 12.93 KB
    __shared__ __align__(8)  float2 wS[HID + 1];                // 0.81 KB
    __shared__ __align__(16) unsigned long long redS[8 * 256];  // 16 KB

    // Prologue-only data aliased into redS (redS used strictly post-mainloop).
    float*  Ms = reinterpret_cast<float*>(redS);               // u64[0..400)
    float4* xi = reinterpret_cast<float4*>(redS + 512);        // 32 float4
    float4* xj = xi + 32;                                      // 32 float4
    float*  ds = reinterpret_cast<float*>(redS + 704);         // 100 floats

    const int tid  = threadIdx.x;
    const int tile = blockIdx.x;
    const int b    = blockIdx.y;
    const int i0   = TCI[tile] * 32;
    const int j0   = TCJ[tile] * 32;

    const int kg  = tid >> 6;        // k-group 0..3
    const int t64 = tid & 63;
    const int tj  = t64 & 7;         // 8 j-groups of 4
    const int ti  = t64 >> 3;        // 8 i-groups of 4

    // --- stage M, d, x tiles, w ---
    for (int q = tid; q < 200; q += 256)
        reinterpret_cast<float4*>(Ms)[q] = reinterpret_cast<const float4*>(g_M)[q];
    if (tid < 32)            xi[tid]      = reinterpret_cast<const float4*>(x)[b * NPTS + i0 + tid];
    else if (tid < 64)       xj[tid - 32] = reinterpret_cast<const float4*>(x)[b * NPTS + j0 + (tid - 32)];
    else if (tid < 89)       reinterpret_cast<float4*>(ds)[tid - 64] =
                                 reinterpret_cast<const float4*>(g_d)[tid - 64];
    if (tid >= 128 && tid < 128 + HID) {
        int q = tid - 128;
        float w = __ldg(W3 + q);
        wS[q] = make_float2(w, w);
    }
    if (tid == 228) wS[HID] = make_float2(0.f, 0.f);   // pad row (prefetch target)
    __syncthreads();

    // --- projection, register-blocked: thread = (k-quad, point ii) ---
    // aS[k][ii] = d[k] + x_i . M[0:4][k];  cS[k][ii] = x_j . M[4:8][k]
    {
        const float4* Ms4 = reinterpret_cast<const float4*>(Ms);
        const float4* ds4 = reinterpret_cast<const float4*>(ds);
        for (int e = tid; e < 25 * 32; e += 256) {
            int kq = e >> 5;          // k-quad 0..24
            int ii = e & 31;
            float4 xv = xi[ii];
            float4 xw = xj[ii];
            float4 a  = ds4[kq];
            float4 c  = make_float4(0.f, 0.f, 0.f, 0.f);
            float4 m;
            m = Ms4[0 * 25 + kq];
            a.x = fmaf(xv.x, m.x, a.x); a.y = fmaf(xv.x, m.y, a.y);
            a.z = fmaf(xv.x, m.z, a.z); a.w = fmaf(xv.x, m.w, a.w);
            m = Ms4[1 * 25 + kq];
            a.x = fmaf(xv.y, m.x, a.x); a.y = fmaf(xv.y, m.y, a.y);
            a.z = fmaf(xv.y, m.z, a.z); a.w = fmaf(xv.y, m.w, a.w);
            m = Ms4[2 * 25 + kq];
            a.x = fmaf(xv.z, m.x, a.x); a.y = fmaf(xv.z, m.y, a.y);
            a.z = fmaf(xv.z, m.z, a.z); a.w = fmaf(xv.z, m.w, a.w);
            m = Ms4[3 * 25 + kq];
            a.x = fmaf(xv.w, m.x, a.x); a.y = fmaf(xv.w, m.y, a.y);
            a.z = fmaf(xv.w, m.z, a.z); a.w = fmaf(xv.w, m.w, a.w);
            m = Ms4[4 * 25 + kq];
            c.x = fmaf(xw.x, m.x, c.x); c.y = fmaf(xw.x, m.y, c.y);
            c.z = fmaf(xw.x, m.z, c.z); c.w = fmaf(xw.x, m.w, c.w);
            m = Ms4[5 * 25 + kq];
            c.x = fmaf(xw.y, m.x, c.x); c.y = fmaf(xw.y, m.y, c.y);
            c.z = fmaf(xw.y, m.z, c.z); c.w = fmaf(xw.y, m.w, c.w);
            m = Ms4[6 * 25 + kq];
            c.x = fmaf(xw.z, m.x, c.x); c.y = fmaf(xw.z, m.y, c.y);
            c.z = fmaf(xw.z, m.z, c.z); c.w = fmaf(xw.z, m.w, c.w);
            m = Ms4[7 * 25 + kq];
            c.x = fmaf(xw.w, m.x, c.x); c.y = fmaf(xw.w, m.y, c.y);
            c.z = fmaf(xw.w, m.z, c.z); c.w = fmaf(xw.w, m.w, c.w);
            int base = kq * 128 + ii;           // (4kq)*32 + ii
            aS[base      ] = a.x;  aS[base + 32] = a.y;
            aS[base +  64] = a.z;  aS[base + 96] = a.w;
            cS[base      ] = c.x;  cS[base + 32] = c.y;
            cS[base +  64] = c.z;  cS[base + 96] = c.w;
        }
        // pad row k=100 (prefetch lands here on the kg=3 strip's last iter)
        if (tid < 32) { aS[HID * 32 + tid] = 0.f; cS[HID * 32 + tid] = 0.f; }
    }
    __syncthreads();   // also fences the redS aliasing

    // --- main loop: 16 slots/thread, 25 k's per group, double-buffered ---
    unsigned long long acc[8] = {0ull,0ull,0ull,0ull,0ull,0ull,0ull,0ull};
    const float* aP = aS + ti * 4;
    const float* cP = cS + tj * 4;
    const unsigned long long* wP = reinterpret_cast<const unsigned long long*>(wS);
    const int k0 = kg * 25;

    float4 a4 = *reinterpret_cast<const float4*>(aP + k0 * 32);
    float4 c4 = *reinterpret_cast<const float4*>(cP + k0 * 32);
    unsigned long long w2 = wP[k0];

    #pragma unroll 5
    for (int k = k0; k < k0 + 25; k++) {
        float4 a4c = a4;
        float4 c4c = c4;
        unsigned long long w2c = w2;
        // prefetch k+1 (in-bounds: padded row at k=100)
        a4 = *reinterpret_cast<const float4*>(aP + (k + 1) * 32);
        c4 = *reinterpret_cast<const float4*>(cP + (k + 1) * 32);
        w2 = wP[k + 1];

        unsigned long long A01 = f2_pack(a4c.x, a4c.y);
        unsigned long long A23 = f2_pack(a4c.z, a4c.w);
        const float cj[4] = {c4c.x, c4c.y, c4c.z, c4c.w};
        #pragma unroll
        for (int jr = 0; jr < 4; jr++) {
            unsigned long long cd = f2_pack(cj[jr], cj[jr]);
            unsigned long long t0 = f2_relu(f2_add(A01, cd));
            unsigned long long t1 = f2_relu(f2_add(A23, cd));
            acc[jr * 2 + 0] = f2_fma(t0, w2c, acc[jr * 2 + 0]);
            acc[jr * 2 + 1] = f2_fma(t1, w2c, acc[jr * 2 + 1]);
        }
    }
    __syncthreads();   // aS/cS consumers done before redS overwrite? (redS separate; sync orders prologue aliasing only)

    // --- all groups publish partials (conflict-free: t64 fastest) ---
    #pragma unroll
    for (int q = 0; q < 8; q++)
        redS[q * 256 + kg * 64 + t64] = acc[q];
    __syncthreads();

    // --- distributed finalize: group kg handles jr = kg, both i-halves ---
    {
        const int jr = kg;
        unsigned long long s0, s1;
        {
            const unsigned long long* r0 = redS + (jr * 2 + 0) * 256 + t64;
            const unsigned long long* r1 = redS + (jr * 2 + 1) * 256 + t64;
            s0 = f2_add(f2_add(r0[0], r0[64]), f2_add(r0[128], r0[192]));
            s1 = f2_add(f2_add(r1[0], r1[64]), f2_add(r1[128], r1[192]));
        }
        const float bias3 = __ldg(b3);
        float* outb = out + (size_t)b * NPAIRS;
        int j = j0 + tj * 4 + jr;
        float v[4];
        f2_unpack(s0, v[0], v[1]);
        f2_unpack(s1, v[2], v[3]);
        #pragma unroll
        for (int pi = 0; pi < 4; pi++) {
            int i = i0 + ti * 4 + pi;
            if (j > i) {
                int rb = i * (NPTS - 1) - ((i * (i - 1)) >> 1) - i - 1;
                float s = bias3 + v[pi];
                outb[rb + j] = __fdividef(1.f, 1.f + __expf(-s));
            }
        }
    }
}

// ---------------------------------------------------------------------------
extern "C" void kernel_launch(void* const* d_in, const int* in_sizes, int n_in,
                              void* d_out, int out_size)
{
    const float* x   = (const float*)d_in[0];
    // d_in[1] = in_hitnr (unused by the reference)
    const float* W1  = (const float*)d_in[2];
    const float* b1  = (const float*)d_in[3];
    const float* W2  = (const float*)d_in[4];
    const float* b2  = (const float*)d_in[5];
    const float* W3  = (const float*)d_in[6];
    const float* b3  = (const float*)d_in[7];
    float* out = (float*)d_out;

    fold_kernel<<<HID, 32>>>(W1, b1, W2, b2);
    pair_kernel<<<dim3(10, BATCH), 256>>>(x, W3, b3, out);
}

// round 15
// speedup vs baseline: 1.4858x; 1.0531x over previous
#include <cuda_runtime.h>
#include <cuda_bf16.h>
#include <math.h>

#define BATCH  64
#define NPTS   128
#define FEAT   4
#define HID    100
#define NPAIRS 8128   // C(128,2)

// Folded weights: g_M[f][k] = sum_t W1[f][t]*W2[t][k] (f 0..7)
//                 g_d[k]    = b2[k] + sum_t b1[t]*W2[t][k]
__device__ __align__(16) float g_M[8 * HID];
__device__ __align__(16) float g_d[HID];

// 32x32 tile list over the 4x4 upper triangle (jt >= it): 10 tiles
__constant__ unsigned char TCI[10] = {0,0,0,0, 1,1,1, 2,2, 3};
__constant__ unsigned char TCJ[10] = {0,1,2,3, 1,2,3, 2,3, 3};

// ---- packed f32x2 helpers (sm_100+) --------------------------------------
__device__ __forceinline__ unsigned long long f2_add(unsigned long long a,
                                                     unsigned long long b) {
    unsigned long long d;
    asm("add.rn.f32x2 %0, %1, %2;" : "=l"(d) : "l"(a), "l"(b));
    return d;
}
__device__ __forceinline__ unsigned long long f2_fma(unsigned long long a,
                                                     unsigned long long b,
                                                     unsigned long long c) {
    unsigned long long d;
    asm("fma.rn.f32x2 %0, %1, %2, %3;" : "=l"(d) : "l"(a), "l"(b), "l"(c));
    return d;
}
__device__ __forceinline__ unsigned long long f2_pack(float lo, float hi) {
    unsigned long long d;
    asm("mov.b64 %0, {%1, %2};" : "=l"(d) : "f"(lo), "f"(hi));
    return d;
}
__device__ __forceinline__ void f2_unpack(unsigned long long v, float& lo, float& hi) {
    asm("mov.b64 {%0, %1}, %2;" : "=f"(lo), "=f"(hi) : "l"(v));
}
__device__ __forceinline__ unsigned long long f2_relu(unsigned long long t) {
    float lo, hi;
    f2_unpack(t, lo, hi);
    lo = fmaxf(lo, 0.f);
    hi = fmaxf(hi, 0.f);
    return f2_pack(lo, hi);
}

// ---------------------------------------------------------------------------
// Kernel 1: fold.  One warp per k (grid 100).  Lane-strided t, shfl-reduce.
// ---------------------------------------------------------------------------
__global__ __launch_bounds__(32)
void fold_kernel(const float* __restrict__ W1,   // [8,100]
                 const float* __restrict__ b1,   // [100]
                 const float* __restrict__ W2,   // [100,100]
                 const float* __restrict__ b2)   // [100]
{
    const int k   = blockIdx.x;
    const int lid = threadIdx.x;

    float acc[9] = {0.f,0.f,0.f,0.f,0.f,0.f,0.f,0.f,0.f};
    #pragma unroll
    for (int tb = 0; tb < 4; tb++) {
        int t = lid + tb * 32;
        if (t < HID) {
            float w2 = W2[t * HID + k];
            #pragma unroll
            for (int f = 0; f < 8; f++)
                acc[f] = fmaf(W1[f * HID + t], w2, acc[f]);
            acc[8] = fmaf(b1[t], w2, acc[8]);
        }
    }
    #pragma unroll
    for (int off = 16; off > 0; off >>= 1) {
        #pragma unroll
        for (int q = 0; q < 9; q++)
            acc[q] += __shfl_down_sync(0xffffffffu, acc[q], off);
    }
    if (lid == 0) {
        #pragma unroll
        for (int f = 0; f < 8; f++)
            g_M[f * HID + k] = acc[f];
        g_d[k] = acc[8] + b2[k];
    }
}

// ---------------------------------------------------------------------------
// Kernel 2: pair tiles with fused projection (R7 structure).  Main loop uses
// the swapped-C trick: the LDS.128 of c4 yields free packed pairs C01/C23;
// only their swaps are packed (2 packs/warp-k instead of 4 dup packs).
// Cell (pi,pj) lives in acc[(pi>>1)*4 + (pj>>1)*2 + ((pi^pj)&1)], lane pi&1.
// 32x32 tile, 256 threads = 4 k-groups x 64.  Grid (10, 64) = 640 CTAs.
// ---------------------------------------------------------------------------
__global__ __launch_bounds__(256, 5)
void pair_kernel(const float* __restrict__ x,    // [64,128,4]
                 const float* __restrict__ W3,   // [100]
                 const float* __restrict__ b3,   // [1]
                 float* __restrict__ out)        // [64, 8128]
{
    __shared__ __align__(16) float aS[HID * 32];                // 12.8 KB
    __shared__ __align__(16) float cS[HID * 32];                // 12.8 KB
    __shared__ __align__(8)  float2 wS[HID];                    // 0.8 KB
    __shared__ __align__(16) unsigned long long redS[8 * 256];  // 16 KB

    // Prologue-only data aliased into redS (redS used strictly post-mainloop).
    float*  Ms = reinterpret_cast<float*>(redS);               // u64[0..400)
    float4* xi = reinterpret_cast<float4*>(redS + 512);        // 32 float4
    float4* xj = xi + 32;                                      // 32 float4
    float*  ds = reinterpret_cast<float*>(redS + 704);         // 100 floats

    const int tid  = threadIdx.x;
    const int tile = blockIdx.x;
    const int b    = blockIdx.y;
    const int i0   = TCI[tile] * 32;
    const int j0   = TCJ[tile] * 32;

    const int kg  = tid >> 6;        // k-group 0..3
    const int t64 = tid & 63;
    const int tj  = t64 & 7;         // 8 j-groups of 4
    const int ti  = t64 >> 3;        // 8 i-groups of 4

    // --- stage M, d, x tiles, w ---
    for (int q = tid; q < 200; q += 256)
        reinterpret_cast<float4*>(Ms)[q] = reinterpret_cast<const float4*>(g_M)[q];
    if (tid < 32)            xi[tid]      = reinterpret_cast<const float4*>(x)[b * NPTS + i0 + tid];
    else if (tid < 64)       xj[tid - 32] = reinterpret_cast<const float4*>(x)[b * NPTS + j0 + (tid - 32)];
    else if (tid < 89)       reinterpret_cast<float4*>(ds)[tid - 64] =
                                 reinterpret_cast<const float4*>(g_d)[tid - 64];
    if (tid >= 128 && tid < 128 + HID) {
        int q = tid - 128;
        float w = __ldg(W3 + q);
        wS[q] = make_float2(w, w);
    }
    __syncthreads();

    // --- projection, register-blocked: thread = (k-quad, point ii) ---
    // aS[k][ii] = d[k] + x_i . M[0:4][k];  cS[k][ii] = x_j . M[4:8][k]
    {
        const float4* Ms4 = reinterpret_cast<const float4*>(Ms);
        const float4* ds4 = reinterpret_cast<const float4*>(ds);
        for (int e = tid; e < 25 * 32; e += 256) {
            int kq = e >> 5;          // k-quad 0..24
            int ii = e & 31;
            float4 xv = xi[ii];
            float4 xw = xj[ii];
            float4 a  = ds4[kq];
            float4 c  = make_float4(0.f, 0.f, 0.f, 0.f);
            float4 m;
            m = Ms4[0 * 25 + kq];
            a.x = fmaf(xv.x, m.x, a.x); a.y = fmaf(xv.x, m.y, a.y);
            a.z = fmaf(xv.x, m.z, a.z); a.w = fmaf(xv.x, m.w, a.w);
            m = Ms4[1 * 25 + kq];
            a.x = fmaf(xv.y, m.x, a.x); a.y = fmaf(xv.y, m.y, a.y);
            a.z = fmaf(xv.y, m.z, a.z); a.w = fmaf(xv.y, m.w, a.w);
            m = Ms4[2 * 25 + kq];
            a.x = fmaf(xv.z, m.x, a.x); a.y = fmaf(xv.z, m.y, a.y);
            a.z = fmaf(xv.z, m.z, a.z); a.w = fmaf(xv.z, m.w, a.w);
            m = Ms4[3 * 25 + kq];
            a.x = fmaf(xv.w, m.x, a.x); a.y = fmaf(xv.w, m.y, a.y);
            a.z = fmaf(xv.w, m.z, a.z); a.w = fmaf(xv.w, m.w, a.w);
            m = Ms4[4 * 25 + kq];
            c.x = fmaf(xw.x, m.x, c.x); c.y = fmaf(xw.x, m.y, c.y);
            c.z = fmaf(xw.x, m.z, c.z); c.w = fmaf(xw.x, m.w, c.w);
            m = Ms4[5 * 25 + kq];
            c.x = fmaf(xw.y, m.x, c.x); c.y = fmaf(xw.y, m.y, c.y);
            c.z = fmaf(xw.y, m.z, c.z); c.w = fmaf(xw.y, m.w, c.w);
            m = Ms4[6 * 25 + kq];
            c.x = fmaf(xw.z, m.x, c.x); c.y = fmaf(xw.z, m.y, c.y);
            c.z = fmaf(xw.z, m.z, c.z); c.w = fmaf(xw.z, m.w, c.w);
            m = Ms4[7 * 25 + kq];
            c.x = fmaf(xw.w, m.x, c.x); c.y = fmaf(xw.w, m.y, c.y);
            c.z = fmaf(xw.w, m.z, c.z); c.w = fmaf(xw.w, m.w, c.w);
            int base = kq * 128 + ii;           // (4kq)*32 + ii
            aS[base      ] = a.x;  aS[base + 32] = a.y;
            aS[base +  64] = a.z;  aS[base + 96] = a.w;
            cS[base      ] = c.x;  cS[base + 32] = c.y;
            cS[base +  64] = c.z;  cS[base + 96] = c.w;
        }
    }
    __syncthreads();   // also fences the redS aliasing

    // --- main loop: 16 cells/thread, 25 k's per group, swapped-C packing ---
    // acc[P*4 + Q*2 + v]: P = i-pair, Q = j-pair, v=0 direct (cells (p0,q0),(p1,q1)),
    // v=1 swapped (cells (p0,q1),(p1,q0)).  Lane = within-pair i bit.
    unsigned long long acc[8] = {0ull,0ull,0ull,0ull,0ull,0ull,0ull,0ull};
    const float* aP = aS + ti * 4;
    const float* cP = cS + tj * 4;
    const unsigned long long* wP = reinterpret_cast<const unsigned long long*>(wS);
    const int kEnd = kg * 25 + 25;

    #pragma unroll 5
    for (int k = kg * 25; k < kEnd; k++) {
        float4 a4 = *reinterpret_cast<const float4*>(aP + k * 32);  // LDS.128
        float4 c4 = *reinterpret_cast<const float4*>(cP + k * 32);  // LDS.128
        unsigned long long w2 = wP[k];                               // LDS.64 bcast
        unsigned long long A01  = f2_pack(a4.x, a4.y);   // free (aligned quads)
        unsigned long long A23  = f2_pack(a4.z, a4.w);
        unsigned long long C01  = f2_pack(c4.x, c4.y);   // free
        unsigned long long C23  = f2_pack(c4.z, c4.w);
        unsigned long long C01s = f2_pack(c4.y, c4.x);   // the only real packs
        unsigned long long C23s = f2_pack(c4.w, c4.z);

        acc[0] = f2_fma(f2_relu(f2_add(A01, C01 )), w2, acc[0]);  // P0 Q0 v0
        acc[1] = f2_fma(f2_relu(f2_add(A01, C01s)), w2, acc[1]);  // P0 Q0 v1
        acc[2] = f2_fma(f2_relu(f2_add(A01, C23 )), w2, acc[2]);  // P0 Q1 v0
        acc[3] = f2_fma(f2_relu(f2_add(A01, C23s)), w2, acc[3]);  // P0 Q1 v1
        acc[4] = f2_fma(f2_relu(f2_add(A23, C01 )), w2, acc[4]);  // P1 Q0 v0
        acc[5] = f2_fma(f2_relu(f2_add(A23, C01s)), w2, acc[5]);  // P1 Q0 v1
        acc[6] = f2_fma(f2_relu(f2_add(A23, C23 )), w2, acc[6]);  // P1 Q1 v0
        acc[7] = f2_fma(f2_relu(f2_add(A23, C23s)), w2, acc[7]);  // P1 Q1 v1
    }

    // --- all groups publish partials (conflict-free: t64 fastest) ---
    #pragma unroll
    for (int q = 0; q < 8; q++)
        redS[q * 256 + kg * 64 + t64] = acc[q];
    __syncthreads();

    // --- distributed finalize: group kg handles the 2x2 cell block
    //     P = kg>>1, Q = kg&1 (acc slots 2kg = v0, 2kg+1 = v1). ---
    {
        const int P = kg >> 1;
        const int Q = kg & 1;
        unsigned long long s0, s1;
        {
            const unsigned long long* r0 = redS + (kg * 2 + 0) * 256 + t64;
            const unsigned long long* r1 = redS + (kg * 2 + 1) * 256 + t64;
            s0 = f2_add(f2_add(r0[0], r0[64]), f2_add(r0[128], r0[192]));  // v0
            s1 = f2_add(f2_add(r1[0], r1[64]), f2_add(r1[128], r1[192]));  // v1
        }
        const float bias3 = __ldg(b3);
        float* outb = out + (size_t)b * NPAIRS;
        const int bi = i0 + ti * 4 + P * 2;     // base i of this cell block
        const int bj = j0 + tj * 4 + Q * 2;     // base j
        float v00, v11, v01, v10;
        f2_unpack(s0, v00, v11);                // v0: (bi,bj), (bi+1,bj+1)
        f2_unpack(s1, v01, v10);                // v1: (bi,bj+1), (bi+1,bj)
        const float cell[2][2] = { {v00, v01}, {v10, v11} };
        #pragma unroll
        for (int di = 0; di < 2; di++) {
            int i  = bi + di;
            int rb = i * (NPTS - 1) - ((i * (i - 1)) >> 1) - i - 1;
            #pragma unroll
            for (int dj = 0; dj < 2; dj++) {
                int j = bj + dj;
                if (j > i) {
                    float s = bias3 + cell[di][dj];
                    outb[rb + j] = __fdividef(1.f, 1.f + __expf(-s));
                }
            }
        }
    }
}

// ---------------------------------------------------------------------------
extern "C" void kernel_launch(void* const* d_in, const int* in_sizes, int n_in,
                              void* d_out, int out_size)
{
    const float* x   = (const float*)d_in[0];
    // d_in[1] = in_hitnr (unused by the reference)
    const float* W1  = (const float*)d_in[2];
    const float* b1  = (const float*)d_in[3];
    const float* W2  = (const float*)d_in[4];
    const float* b2  = (const float*)d_in[5];
    const float* W3  = (const float*)d_in[6];
    const float* b3  = (const float*)d_in[7];
    float* out = (float*)d_out;

    fold_kernel<<<HID, 32>>>(W1, b1, W2, b2);
    pair_kernel<<<dim3(10, BATCH), 256>>>(x, W3, b3, out);
}